// round 1
// baseline (speedup 1.0000x reference)
#include <cuda_runtime.h>
#include <cstdint>

#define BATCH 8
#define NN    2048
#define CC    128
#define EPSV  0.1f

typedef unsigned long long ull;

// Scratch (static device globals — no runtime allocation)
__device__ float g_h[BATCH * NN * CC];   // 8.4 MB, fits L2
__device__ float g_al[BATCH * NN];
__device__ float g_ar[BATCH * NN];

__device__ __forceinline__ ull pack2(float x, float y) {
    ull r; asm("mov.b64 %0, {%1, %2};" : "=l"(r) : "f"(x), "f"(y)); return r;
}
__device__ __forceinline__ float2 unpack2(ull v) {
    float2 r; asm("mov.b64 {%0, %1}, %2;" : "=f"(r.x), "=f"(r.y) : "l"(v)); return r;
}
// packed dual-fp32 FMA (sm_100+): d = a*b + c on both lanes
__device__ __forceinline__ ull fma2(ull a, ull b, ull c) {
    ull d; asm("fma.rn.f32x2 %0, %1, %2, %3;" : "=l"(d) : "l"(a), "l"(b), "l"(c)); return d;
}
__device__ __forceinline__ float tanh_fast(float x) {
    float y; asm("tanh.approx.f32 %0, %1;" : "=f"(y) : "f"(x)); return y;
}

// ---------------------------------------------------------------------------
// Kernel 1: h[n][o] = sum_k x[n][k] * W[k][o]   (rows flattened: 16384 x 128)
// Block = 128 threads, 16 rows. x tile transposed in smem so row-pairs are
// contiguous for f32x2; W staged in 32-row chunks.
// ---------------------------------------------------------------------------
__global__ void __launch_bounds__(128) prep_kernel(const float* __restrict__ x,
                                                   const float* __restrict__ W) {
    __shared__ __align__(16) float sXT[CC][18];   // [k][row] padded (2-way conflicts max)
    __shared__ __align__(16) float sW[32][CC];
    const int tid = threadIdx.x;
    const int row0 = blockIdx.x * 16;

    // load x tile transposed: sXT[k][r] = x[row0+r][k]
#pragma unroll
    for (int q = 0; q < 16; q++)
        sXT[tid][q] = x[(size_t)(row0 + q) * CC + tid];

    ull acc[8];
#pragma unroll
    for (int p = 0; p < 8; p++) acc[p] = 0ull;

    for (int kc = 0; kc < 4; kc++) {
        __syncthreads();
        const float4* Wg4 = (const float4*)(W + (size_t)kc * 32 * CC);
        float4* sW4 = (float4*)sW;
#pragma unroll
        for (int q = 0; q < 8; q++) sW4[q * 128 + tid] = Wg4[q * 128 + tid];
        __syncthreads();
#pragma unroll 8
        for (int k2 = 0; k2 < 32; k2++) {
            const int k = kc * 32 + k2;
            const float w = sW[k2][tid];
            const ull ww = pack2(w, w);
#pragma unroll
            for (int p = 0; p < 8; p++) {
                const ull xp = *(const ull*)&sXT[k][2 * p];  // rows (2p, 2p+1), broadcast
                acc[p] = fma2(xp, ww, acc[p]);
            }
        }
    }
#pragma unroll
    for (int p = 0; p < 8; p++) {
        const float2 v = unpack2(acc[p]);
        g_h[(size_t)(row0 + 2 * p)     * CC + tid] = v.x;
        g_h[(size_t)(row0 + 2 * p + 1) * CC + tid] = v.y;
    }
}

// ---------------------------------------------------------------------------
// Kernel 2: alpha_l[row] = h[row]·w_att_l, alpha_r likewise. One warp per row.
// ---------------------------------------------------------------------------
__global__ void attred_kernel(const float* __restrict__ wl,
                              const float* __restrict__ wr) {
    const int gtid = blockIdx.x * blockDim.x + threadIdx.x;
    const int warp = gtid >> 5;
    const int lane = gtid & 31;
    const float4 hv  = *(const float4*)&g_h[(size_t)warp * CC + lane * 4];
    const float4 wlv = *(const float4*)&wl[lane * 4];
    const float4 wrv = *(const float4*)&wr[lane * 4];
    float pl = hv.x * wlv.x + hv.y * wlv.y + hv.z * wlv.z + hv.w * wlv.w;
    float pr = hv.x * wrv.x + hv.y * wrv.y + hv.z * wrv.z + hv.w * wrv.w;
#pragma unroll
    for (int off = 16; off; off >>= 1) {
        pl += __shfl_down_sync(0xffffffffu, pl, off);
        pr += __shfl_down_sync(0xffffffffu, pr, off);
    }
    if (lane == 0) { g_al[warp] = pl; g_ar[warp] = pr; }
}

// ---------------------------------------------------------------------------
// Kernel 3 (fused main): per block: 32 i-rows x 128 cols of out for one batch.
// Loop over 64 j-tiles of 32: build masked alpha tile in smem, then
// register-blocked f32x2 MAC: thread = 4 cols (o-pairs) x 8 rows.
// ---------------------------------------------------------------------------
__global__ void __launch_bounds__(128, 8)
fagcn_main(const int* __restrict__ adj, const float* __restrict__ x0,
           float* __restrict__ out) {
    __shared__ __align__(16) float sH[32][CC];     // 16 KB
    __shared__ float sAlpha[32][33];               // [i][jj], padded
    __shared__ float sAr[32];

    const int tid  = threadIdx.x;
    const int lane = tid & 31;
    const int ty   = tid >> 5;                     // 0..3
    const int b    = blockIdx.x >> 6;              // 64 i-tiles per batch
    const int i0   = (blockIdx.x & 63) * 32;

    const float* hb   = g_h + (size_t)b * NN * CC;
    const int*   adjb = adj + (size_t)(b * NN + i0) * NN;

    if (tid < 32) sAr[tid] = g_ar[b * NN + i0 + tid];

    ull acc[8][2];
#pragma unroll
    for (int r = 0; r < 8; r++) { acc[r][0] = 0ull; acc[r][1] = 0ull; }

    __syncthreads();

    // hoist loop-invariant alpha_r values (i = 4r+ty fixed per thread)
    float arv[8];
#pragma unroll
    for (int r = 0; r < 8; r++) arv[r] = sAr[r * 4 + ty];

    for (int jt = 0; jt < 64; jt++) {
        const int j0 = jt * 32;

        // stage h j-tile: 32 rows x 128 floats = 1024 float4
        const float4* hsrc = (const float4*)(hb + (size_t)j0 * CC);
        float4* hdst = (float4*)sH;
#pragma unroll
        for (int q = 0; q < 8; q++) hdst[q * 128 + tid] = hsrc[q * 128 + tid];

        // alpha tile: thread handles jj = lane (fixed), i = 4r+ty
        const float alv = g_al[b * NN + j0 + lane];
#pragma unroll
        for (int r = 0; r < 8; r++) {
            const int i = r * 4 + ty;
            const int av = adjb[(size_t)i * NN + j0 + lane];   // coalesced
            const float t = tanh_fast(arv[r] * alv);
            sAlpha[i][lane] = av ? t : 0.0f;                   // conflict-free
        }
        __syncthreads();

#pragma unroll 8
        for (int jj = 0; jj < 32; jj++) {
            const ulonglong2 hv = *(const ulonglong2*)&sH[jj][lane * 4];  // LDS.128
#pragma unroll
            for (int r = 0; r < 8; r++) {
                const float a = sAlpha[ty * 8 + r][jj];        // warp-broadcast
                const ull aa = pack2(a, a);
                acc[r][0] = fma2(aa, hv.x, acc[r][0]);
                acc[r][1] = fma2(aa, hv.y, acc[r][1]);
            }
        }
        __syncthreads();
    }

    // epilogue: out = acc + EPS * x_0
#pragma unroll
    for (int r = 0; r < 8; r++) {
        const int row = i0 + ty * 8 + r;
        const size_t base = ((size_t)(b * NN + row)) * CC + lane * 4;
        const float4 xv = *(const float4*)&x0[base];
        const float2 p0 = unpack2(acc[r][0]);
        const float2 p1 = unpack2(acc[r][1]);
        float4 o;
        o.x = p0.x + EPSV * xv.x;
        o.y = p0.y + EPSV * xv.y;
        o.z = p1.x + EPSV * xv.z;
        o.w = p1.y + EPSV * xv.w;
        *(float4*)&out[base] = o;
    }
}

extern "C" void kernel_launch(void* const* d_in, const int* in_sizes, int n_in,
                              void* d_out, int out_size) {
    const float* x   = (const float*)d_in[0];
    const float* x0  = (const float*)d_in[1];
    const int*   adj = (const int*)d_in[2];
    const float* W   = (const float*)d_in[3];
    const float* wl  = (const float*)d_in[4];
    const float* wr  = (const float*)d_in[5];
    float* out = (float*)d_out;

    prep_kernel<<<BATCH * NN / 16, 128>>>(x, W);
    attred_kernel<<<BATCH * NN / 8, 256>>>(wl, wr);
    fagcn_main<<<BATCH * (NN / 32), 128>>>(adj, x0, out);
}